// round 1
// baseline (speedup 1.0000x reference)
#include <cuda_runtime.h>

#define B_   2
#define L_   2048
#define D_   1024
#define H_   16
#define DH_  64
#define M_   (B_*L_)          // 4096 rows
#define SCALE 0.125f          // 1/sqrt(64)

#define QB   16               // q rows per attention block
#define KC   256              // k chunk
#define KS_STRIDE 260         // padded stride for transposed K chunk (mult of 4)

// ---------------- scratch (static device memory; no allocs) ----------------
__device__ float g_q[M_*D_];
__device__ float g_k[M_*D_];
__device__ float g_v[M_*D_];
__device__ float g_ctx[M_*D_];

// ---------------- fused QKV GEMM: Y = X @ W^T + b, head-major output -------
__global__ __launch_bounds__(256)
void qkv_gemm(const float* __restrict__ X,
              const float* __restrict__ W0, const float* __restrict__ b0,
              const float* __restrict__ W1, const float* __restrict__ b1,
              const float* __restrict__ W2, const float* __restrict__ b2)
{
    __shared__ float As[16][64];
    __shared__ float Bs[16][64];

    const int mat = blockIdx.z;
    const float* W  = (mat == 0) ? W0 : ((mat == 1) ? W1 : W2);
    const float* bi = (mat == 0) ? b0 : ((mat == 1) ? b1 : b2);
    float* out = (mat == 0) ? g_q : ((mat == 1) ? g_k : g_v);

    const int row0 = blockIdx.x * 64;
    const int col0 = blockIdx.y * 64;
    const int tid = threadIdx.x;
    const int tx = tid & 15, ty = tid >> 4;

    float acc[4][4] = {};

    for (int k0 = 0; k0 < D_; k0 += 16) {
        #pragma unroll
        for (int i = 0; i < 4; i++) {
            int idx = tid + i * 256;
            int m = idx >> 4, kk = idx & 15;
            As[kk][m] = X[(row0 + m) * D_ + k0 + kk];
        }
        #pragma unroll
        for (int i = 0; i < 4; i++) {
            int idx = tid + i * 256;
            int n = idx >> 4, kk = idx & 15;
            Bs[kk][n] = W[(col0 + n) * D_ + k0 + kk];
        }
        __syncthreads();
        #pragma unroll
        for (int kk = 0; kk < 16; kk++) {
            float a[4], b[4];
            #pragma unroll
            for (int i = 0; i < 4; i++) a[i] = As[kk][ty * 4 + i];
            #pragma unroll
            for (int j = 0; j < 4; j++) b[j] = Bs[kk][tx * 4 + j];
            #pragma unroll
            for (int i = 0; i < 4; i++)
                #pragma unroll
                for (int j = 0; j < 4; j++)
                    acc[i][j] += a[i] * b[j];
        }
        __syncthreads();
    }

    // write into [B, H, L, DH] layout
    #pragma unroll
    for (int i = 0; i < 4; i++) {
        int row = row0 + ty * 4 + i;
        int bb = row / L_, l = row % L_;
        #pragma unroll
        for (int j = 0; j < 4; j++) {
            int col = col0 + tx * 4 + j;
            int h = col >> 6, d = col & 63;
            out[(((size_t)bb * H_ + h) * L_ + l) * DH_ + d] = acc[i][j] + bi[col];
        }
    }
}

// ---------------- output projection GEMM: out = ctx @ Wo^T + bo ------------
__global__ __launch_bounds__(256)
void out_gemm(const float* __restrict__ W, const float* __restrict__ bi,
              float* __restrict__ out)
{
    __shared__ float As[16][64];
    __shared__ float Bs[16][64];

    const int row0 = blockIdx.x * 64;
    const int col0 = blockIdx.y * 64;
    const int tid = threadIdx.x;
    const int tx = tid & 15, ty = tid >> 4;

    float acc[4][4] = {};

    for (int k0 = 0; k0 < D_; k0 += 16) {
        #pragma unroll
        for (int i = 0; i < 4; i++) {
            int idx = tid + i * 256;
            int m = idx >> 4, kk = idx & 15;
            As[kk][m] = g_ctx[(row0 + m) * D_ + k0 + kk];
        }
        #pragma unroll
        for (int i = 0; i < 4; i++) {
            int idx = tid + i * 256;
            int n = idx >> 4, kk = idx & 15;
            Bs[kk][n] = W[(col0 + n) * D_ + k0 + kk];
        }
        __syncthreads();
        #pragma unroll
        for (int kk = 0; kk < 16; kk++) {
            float a[4], b[4];
            #pragma unroll
            for (int i = 0; i < 4; i++) a[i] = As[kk][ty * 4 + i];
            #pragma unroll
            for (int j = 0; j < 4; j++) b[j] = Bs[kk][tx * 4 + j];
            #pragma unroll
            for (int i = 0; i < 4; i++)
                #pragma unroll
                for (int j = 0; j < 4; j++)
                    acc[i][j] += a[i] * b[j];
        }
        __syncthreads();
    }

    #pragma unroll
    for (int i = 0; i < 4; i++) {
        int row = row0 + ty * 4 + i;
        #pragma unroll
        for (int j = 0; j < 4; j++) {
            int col = col0 + tx * 4 + j;
            out[(size_t)row * D_ + col] = acc[i][j] + bi[col];
        }
    }
}

// ---------------- fused attention: scores -> softmax -> weights + ctx ------
// grid: (L/QB, H, B), block: 256 threads
// dyn smem: scr[QB][L] | Qs[DH][QB] | kv[64*KS_STRIDE]
#define SMEM_FLOATS (QB*L_ + DH_*QB + 64*KS_STRIDE)
#define SMEM_BYTES  (SMEM_FLOATS * 4)

__global__ __launch_bounds__(256)
void attn_kernel(float* __restrict__ attn_out)
{
    extern __shared__ float smem[];
    float* scr = smem;                    // QB * 2048
    float* Qs  = smem + QB * L_;          // 64 * 16 (d-major)
    float* kv  = Qs + DH_ * QB;           // K chunk (transposed) / V chunk / partials

    const int q0 = blockIdx.x * QB;
    const int hh = blockIdx.y;
    const int bb = blockIdx.z;
    const int tid = threadIdx.x;

    const size_t head_base = ((size_t)bb * H_ + hh) * L_ * DH_;
    const float* Qh = g_q + head_base;
    const float* Kh = g_k + head_base;
    const float* Vh = g_v + head_base;

    // load Q tile transposed (d-major), pre-scaled
    for (int i = tid; i < QB * DH_; i += 256) {
        int q = i >> 6, d = i & 63;
        Qs[d * QB + q] = Qh[(q0 + q) * DH_ + d] * SCALE;
    }

    // ---- phase 1: scores = Q @ K^T * scale (into scr) ----
    {
        const int qg = tid >> 6;   // 0..3  -> q rows qg*4..qg*4+3
        const int kg = tid & 63;   // 0..63 -> k cols kg*4..kg*4+3
        for (int kc = 0; kc < L_; kc += KC) {
            __syncthreads();
            // load K chunk transposed: kv[d * KS_STRIDE + k]
            for (int i4 = tid; i4 < KC * DH_ / 4; i4 += 256) {
                int k  = i4 >> 4;
                int d4 = (i4 & 15) * 4;
                float4 t = *(const float4*)(Kh + (size_t)(kc + k) * DH_ + d4);
                kv[(d4 + 0) * KS_STRIDE + k] = t.x;
                kv[(d4 + 1) * KS_STRIDE + k] = t.y;
                kv[(d4 + 2) * KS_STRIDE + k] = t.z;
                kv[(d4 + 3) * KS_STRIDE + k] = t.w;
            }
            __syncthreads();

            float acc[4][4] = {};
            #pragma unroll 8
            for (int d = 0; d < DH_; d++) {
                float4 a4 = *(const float4*)(Qs + d * QB + qg * 4);
                float4 b4 = *(const float4*)(kv + d * KS_STRIDE + kg * 4);
                acc[0][0] += a4.x*b4.x; acc[0][1] += a4.x*b4.y; acc[0][2] += a4.x*b4.z; acc[0][3] += a4.x*b4.w;
                acc[1][0] += a4.y*b4.x; acc[1][1] += a4.y*b4.y; acc[1][2] += a4.y*b4.z; acc[1][3] += a4.y*b4.w;
                acc[2][0] += a4.z*b4.x; acc[2][1] += a4.z*b4.y; acc[2][2] += a4.z*b4.z; acc[2][3] += a4.z*b4.w;
                acc[3][0] += a4.w*b4.x; acc[3][1] += a4.w*b4.y; acc[3][2] += a4.w*b4.z; acc[3][3] += a4.w*b4.w;
            }
            #pragma unroll
            for (int i = 0; i < 4; i++)
                *(float4*)(scr + (qg * 4 + i) * L_ + kc + kg * 4) =
                    make_float4(acc[i][0], acc[i][1], acc[i][2], acc[i][3]);
        }
    }
    __syncthreads();

    // ---- phase 2: softmax per row + write attn weights ----
    {
        const int warp = tid >> 5, lane = tid & 31;
        for (int r = warp; r < QB; r += 8) {
            float* row = scr + r * L_;
            float m = -1e30f;
            for (int k = lane; k < L_; k += 32) m = fmaxf(m, row[k]);
            #pragma unroll
            for (int o = 16; o; o >>= 1) m = fmaxf(m, __shfl_xor_sync(0xffffffffu, m, o));
            float s = 0.f;
            for (int k = lane; k < L_; k += 32) {
                float e = __expf(row[k] - m);
                row[k] = e;
                s += e;
            }
            #pragma unroll
            for (int o = 16; o; o >>= 1) s += __shfl_xor_sync(0xffffffffu, s, o);
            float inv = 1.f / s;
            float* g = attn_out + (((size_t)bb * H_ + hh) * L_ + q0 + r) * L_;
            for (int k = lane; k < L_; k += 32) {
                float w = row[k] * inv;
                row[k] = w;
                g[k] = w;
            }
        }
    }

    // ---- phase 3: ctx = W @ V (4-way k-split, partials reduced in smem) ----
    {
        const int kslice = tid >> 6;       // 0..3
        const int pos = tid & 63;
        const int qg = pos >> 4;           // 0..3 -> q rows qg*4..+3
        const int dg = pos & 15;           // 0..15 -> d cols dg*4..+3
        float acc[4][4] = {};

        for (int kc = 0; kc < L_; kc += KC) {
            __syncthreads();
            // load V chunk straight: kv[k*64 + d]
            for (int i4 = tid; i4 < KC * DH_ / 4; i4 += 256)
                ((float4*)kv)[i4] = ((const float4*)(Vh + (size_t)kc * DH_))[i4];
            __syncthreads();

            const int kb = kslice * 64;
            #pragma unroll 4
            for (int kk = 0; kk < 64; kk++) {
                int k = kb + kk;
                float4 v4 = *(const float4*)(kv + k * DH_ + dg * 4);
                #pragma unroll
                for (int i = 0; i < 4; i++) {
                    float w = scr[(qg * 4 + i) * L_ + kc + k];
                    acc[i][0] += w * v4.x;
                    acc[i][1] += w * v4.y;
                    acc[i][2] += w * v4.z;
                    acc[i][3] += w * v4.w;
                }
            }
        }
        __syncthreads();
        // dump partials: kv[slice*1024 + q*64 + d]
        #pragma unroll
        for (int i = 0; i < 4; i++)
            #pragma unroll
            for (int j = 0; j < 4; j++)
                kv[kslice * 1024 + (qg * 4 + i) * 64 + dg * 4 + j] = acc[i][j];
        __syncthreads();
        // reduce 4 slices, write ctx in [B, L, D] layout
        for (int p = tid; p < QB * DH_; p += 256) {
            float v = kv[p] + kv[p + 1024] + kv[p + 2048] + kv[p + 3072];
            int ql = p >> 6, d = p & 63;
            g_ctx[((size_t)bb * L_ + q0 + ql) * D_ + hh * DH_ + d] = v;
        }
    }
}

// ---------------- launch ----------------
extern "C" void kernel_launch(void* const* d_in, const int* in_sizes, int n_in,
                              void* d_out, int out_size)
{
    const float* x  = (const float*)d_in[0];
    const float* Wq = (const float*)d_in[1];
    const float* bq = (const float*)d_in[2];
    const float* Wk = (const float*)d_in[3];
    const float* bk = (const float*)d_in[4];
    const float* Wv = (const float*)d_in[5];
    const float* bv = (const float*)d_in[6];
    const float* Wo = (const float*)d_in[7];
    const float* bo = (const float*)d_in[8];

    float* out  = (float*)d_out;                       // [B, L, D]
    float* attn = out + (size_t)M_ * D_;               // [B, H, L, L]

    cudaFuncSetAttribute(attn_kernel,
                         cudaFuncAttributeMaxDynamicSharedMemorySize, SMEM_BYTES);

    dim3 g1(M_ / 64, D_ / 64, 3);
    qkv_gemm<<<g1, 256>>>(x, Wq, bq, Wk, bk, Wv, bv);

    dim3 g2(L_ / QB, H_, B_);
    attn_kernel<<<g2, 256, SMEM_BYTES>>>(attn);

    dim3 g3(M_ / 64, D_ / 64, 1);
    out_gemm<<<g3, 256>>>(Wo, bo, out);
}

// round 8
// speedup vs baseline: 1.3527x; 1.3527x over previous
#include <cuda_runtime.h>
#include <cuda_bf16.h>
#include <mma.h>
#include <cstdint>

using namespace nvcuda;

#define B_   2
#define L_   2048
#define D_   1024
#define H_   16
#define DH_  64
#define M_   (B_*L_)          // 4096 rows
#define K2_  2048             // split-K (hi/lo interleaved)
#define SCALE 0.125f          // 1/sqrt(64)

// ---------------- scratch (static device memory; no allocs) ----------------
__device__ float g_q[M_*D_];
__device__ float g_k[M_*D_];
__device__ float g_v[M_*D_];
__device__ float g_ctx[M_*D_];
__device__ __nv_bfloat16 g_xs [M_*K2_];
__device__ __nv_bfloat16 g_cs [M_*K2_];
__device__ __nv_bfloat16 g_wqs[D_*K2_];   // weights, (hi,lo) interleaved
__device__ __nv_bfloat16 g_wks[D_*K2_];
__device__ __nv_bfloat16 g_wvs[D_*K2_];
__device__ __nv_bfloat16 g_wos[D_*K2_];
__device__ __nv_bfloat16 g_wqw[D_*K2_];   // weights, (lo,hi) swapped
__device__ __nv_bfloat16 g_wkw[D_*K2_];
__device__ __nv_bfloat16 g_wvw[D_*K2_];
__device__ __nv_bfloat16 g_wow[D_*K2_];

// ---------------- hi/lo bf16 pair packing (no local-array UB) --------------
__device__ __forceinline__ uint32_t pack_hl(float x) {
    __nv_bfloat16 h = __float2bfloat16(x);
    __nv_bfloat16 l = __float2bfloat16(x - __bfloat162float(h));
    return (uint32_t)__bfloat16_as_ushort(h) |
           ((uint32_t)__bfloat16_as_ushort(l) << 16);
}
__device__ __forceinline__ uint32_t pack_lh(float x) {
    __nv_bfloat16 h = __float2bfloat16(x);
    __nv_bfloat16 l = __float2bfloat16(x - __bfloat162float(h));
    return (uint32_t)__bfloat16_as_ushort(l) |
           ((uint32_t)__bfloat16_as_ushort(h) << 16);
}

// ---------------- split kernels: fp32 -> bf16 (hi,lo) pairs ----------------
// src_tag: 0 = use src param (harness pointer), 1 = g_ctx (device symbol,
// resolved IN DEVICE CODE — passing g_ctx from host was the R3-R7 bug).
// dst_tag: 0 = g_xs, 1 = g_cs
__global__ __launch_bounds__(256)
void split_act(const float* __restrict__ src_param, int src_tag, int dst_tag, int n4)
{
    const float* src = (src_tag == 0) ? src_param : g_ctx;
    __nv_bfloat16* dst = (dst_tag == 0) ? g_xs : g_cs;
    int i = blockIdx.x * 256 + threadIdx.x;
    if (i >= n4) return;
    float4 v = ((const float4*)src)[i];
    uint4 o;
    o.x = pack_hl(v.x);
    o.y = pack_hl(v.y);
    o.z = pack_hl(v.z);
    o.w = pack_hl(v.w);
    ((uint4*)dst)[i] = o;
}

// Weight split: writes BOTH (hi,lo) and (lo,hi) arrays. tag: 0=wq 1=wk 2=wv 3=wo
__global__ __launch_bounds__(256)
void split_w(const float* __restrict__ src, int tag, int n4)
{
    __nv_bfloat16* dn = tag == 0 ? g_wqs : tag == 1 ? g_wks : tag == 2 ? g_wvs : g_wos;
    __nv_bfloat16* ds = tag == 0 ? g_wqw : tag == 1 ? g_wkw : tag == 2 ? g_wvw : g_wow;
    int i = blockIdx.x * 256 + threadIdx.x;
    if (i >= n4) return;
    float4 v = ((const float4*)src)[i];
    uint4 on, os;
    on.x = pack_hl(v.x); os.x = pack_lh(v.x);
    on.y = pack_hl(v.y); os.y = pack_lh(v.y);
    on.z = pack_hl(v.z); os.z = pack_lh(v.z);
    on.w = pack_hl(v.w); os.w = pack_lh(v.w);
    ((uint4*)dn)[i] = on;
    ((uint4*)ds)[i] = os;
}

// ---------------- WMMA GEMM: Y[M,N] = A @ B^T (+bias), exact 2-pass --------
// A: [Mrows, K2] bf16 (hi,lo) interleaved; pass 0 uses B=(hi,lo), pass 1 B=(lo,hi).
// which: 0 = qkv (blockIdx.z selects matrix; writes g_q/g_k/g_v head-major)
//        1 = out projection (writes out_dst row-major [M_, D_])
#define TM 128
#define TN 128
#define BK 32
#define NCH (K2_ / BK)        // 64
#define AS 40                 // smem row stride in bf16 (80B; mult of 8 for wmma)
#define STG 20                // epilogue stage ldm (mult of 4 for wmma float store)

__global__ __launch_bounds__(256)
void mma_gemm(int which,
              const float* __restrict__ bi0, const float* __restrict__ bi1,
              const float* __restrict__ bi2, float* __restrict__ out_dst)
{
    __shared__ __align__(16) __nv_bfloat16 sA[TM][AS];
    __shared__ __align__(16) __nv_bfloat16 sB[TN][AS];
    __shared__ __align__(16) float stage[8][16 * STG];   // per-warp epilogue staging

    const int mat = blockIdx.z;
    const __nv_bfloat16* A = (which == 0) ? g_xs : g_cs;
    const __nv_bfloat16* Bn =
        (which == 1) ? g_wos : (mat == 0 ? g_wqs : (mat == 1 ? g_wks : g_wvs));
    const __nv_bfloat16* Bw =
        (which == 1) ? g_wow : (mat == 0 ? g_wqw : (mat == 1 ? g_wkw : g_wvw));
    const float* bias = (mat == 0) ? bi0 : (mat == 1 ? bi1 : bi2);
    float* dsel = (mat == 0) ? g_q : (mat == 1 ? g_k : g_v);

    const int row0 = blockIdx.x * TM;
    const int col0 = blockIdx.y * TN;
    const int tid  = threadIdx.x;
    const int wid  = tid >> 5, lane = tid & 31;
    const int wr   = wid >> 2;          // 0..1  -> 64-row band
    const int wc   = wid & 3;           // 0..3  -> 32-col band

    // accumulators: warp tile 64x32 = 4x2 wmma 16x16 tiles
    wmma::fragment<wmma::accumulator, 16, 16, 16, float> acc[4][2];
    #pragma unroll
    for (int i = 0; i < 4; i++)
        #pragma unroll
        for (int j = 0; j < 2; j++)
            wmma::fill_fragment(acc[i][j], 0.0f);

    // tile-copy indices: 512 uint4 per operand tile, 2 per thread
    const int r0c = tid >> 2,          q0c = tid & 3;
    const int r1c = (tid + 256) >> 2,  q1c = (tid + 256) & 3;

    for (int pass = 0; pass < 2; pass++) {
        const __nv_bfloat16* Bp = pass ? Bw : Bn;

        for (int ch = 0; ch < NCH; ch++) {
            const int k0g = ch * BK;
            __syncthreads();     // previous compute done before overwriting tiles
            *(uint4*)&sA[r0c][q0c * 8] =
                *(const uint4*)(A  + (size_t)(row0 + r0c) * K2_ + k0g + q0c * 8);
            *(uint4*)&sA[r1c][q1c * 8] =
                *(const uint4*)(A  + (size_t)(row0 + r1c) * K2_ + k0g + q1c * 8);
            *(uint4*)&sB[r0c][q0c * 8] =
                *(const uint4*)(Bp + (size_t)(col0 + r0c) * K2_ + k0g + q0c * 8);
            *(uint4*)&sB[r1c][q1c * 8] =
                *(const uint4*)(Bp + (size_t)(col0 + r1c) * K2_ + k0g + q1c * 8);
            __syncthreads();

            #pragma unroll
            for (int kk = 0; kk < 2; kk++) {
                const int k0 = kk * 16;
                wmma::fragment<wmma::matrix_a, 16, 16, 16, __nv_bfloat16,
                               wmma::row_major> af[4];
                #pragma unroll
                for (int i = 0; i < 4; i++)
                    wmma::load_matrix_sync(af[i], &sA[wr * 64 + i * 16][k0], AS);
                // B stored [n][k]; as K x N col-major matrix: elem(k,n) at n*AS + k
                wmma::fragment<wmma::matrix_b, 16, 16, 16, __nv_bfloat16,
                               wmma::col_major> bf[2];
                #pragma unroll
                for (int j = 0; j < 2; j++)
                    wmma::load_matrix_sync(bf[j], &sB[wc * 32 + j * 16][k0], AS);
                #pragma unroll
                for (int i = 0; i < 4; i++)
                    #pragma unroll
                    for (int j = 0; j < 2; j++)
                        wmma::mma_sync(acc[i][j], af[i], bf[j], acc[i][j]);
            }
        }
    }

    // ---- epilogue: fragment -> smem stage (explicit indexing) -> gmem ----
    __syncthreads();
    #pragma unroll
    for (int i = 0; i < 4; i++) {
        #pragma unroll
        for (int j = 0; j < 2; j++) {
            wmma::store_matrix_sync(&stage[wid][0], acc[i][j], STG,
                                    wmma::mem_row_major);
            __syncwarp();
            // 256 elements, 8 per lane
            #pragma unroll
            for (int e = 0; e < 8; e++) {
                int idx = lane * 8 + e;
                int rr = idx >> 4, cc = idx & 15;
                int m = row0 + wr * 64 + i * 16 + rr;
                int n = col0 + wc * 32 + j * 16 + cc;
                float v = stage[wid][rr * STG + cc] + bias[n];
                if (which == 1) {
                    out_dst[(size_t)m * D_ + n] = v;
                } else {
                    int l = m & (L_ - 1), bb = m >> 11;
                    int h = n >> 6, d = n & 63;
                    dsel[(((size_t)bb * H_ + h) * L_ + l) * DH_ + d] = v;
                }
            }
            __syncwarp();
        }
    }
}

// ---------------- fused attention: scores -> softmax -> weights + ctx ------
#define QB   16
#define KC   256
#define KS_STRIDE 260
#define SMEM_FLOATS (QB*L_ + DH_*QB + 64*KS_STRIDE)
#define SMEM_BYTES  (SMEM_FLOATS * 4)

__global__ __launch_bounds__(256)
void attn_kernel(float* __restrict__ attn_out)
{
    extern __shared__ float smem[];
    float* scr = smem;                    // QB * 2048
    float* Qs  = smem + QB * L_;          // 64 * 16 (d-major)
    float* kv  = Qs + DH_ * QB;           // K chunk (transposed) / V chunk / partials

    const int q0 = blockIdx.x * QB;
    const int hh = blockIdx.y;
    const int bb = blockIdx.z;
    const int tid = threadIdx.x;

    const size_t head_base = ((size_t)bb * H_ + hh) * L_ * DH_;
    const float* Qh = g_q + head_base;
    const float* Kh = g_k + head_base;
    const float* Vh = g_v + head_base;

    for (int i = tid; i < QB * DH_; i += 256) {
        int q = i >> 6, d = i & 63;
        Qs[d * QB + q] = Qh[(q0 + q) * DH_ + d] * SCALE;
    }

    // ---- phase 1: scores = Q @ K^T ----
    {
        const int qg = tid >> 6;
        const int kg = tid & 63;
        for (int kc = 0; kc < L_; kc += KC) {
            __syncthreads();
            for (int i4 = tid; i4 < KC * DH_ / 4; i4 += 256) {
                int k  = i4 >> 4;
                int d4 = (i4 & 15) * 4;
                float4 t = *(const float4*)(Kh + (size_t)(kc + k) * DH_ + d4);
                kv[(d4 + 0) * KS_STRIDE + k] = t.x;
                kv[(d4 + 1) * KS_STRIDE + k] = t.y;
                kv[(d4 + 2) * KS_STRIDE + k] = t.z;
                kv[(d4 + 3) * KS_STRIDE + k] = t.w;
            }
            __syncthreads();

            float acc[4][4] = {};
            #pragma unroll 8
            for (int d = 0; d < DH_; d++) {
                float4 a4 = *(const float4*)(Qs + d * QB + qg * 4);
                float4 b4 = *(const float4*)(kv + d * KS_STRIDE + kg * 4);
                acc[0][0] += a4.x*b4.x; acc[0][1] += a4.x*b4.y; acc[0][2] += a4.x*b4.z; acc[0][3] += a4.x*b4.w;
                acc[1][0] += a4.y*b4.x; acc[1][1] += a4.y*b4.y; acc[1][2] += a4.y*b4.z; acc[1][3] += a4.y*b4.w;
                acc[2][0] += a4.z*b4.x; acc[2][1] += a4.z*b4.y; acc[2][2] += a4.z*b4.z; acc[2][3] += a4.z*b4.w;
                acc[3][0] += a4.w*b4.x; acc[3][1] += a4.w*b4.y; acc[3][2] += a4.w*b4.z; acc[3][3] += a4.w*b4.w;
            }
            #pragma unroll
            for (int i = 0; i < 4; i++)
                *(float4*)(scr + (qg * 4 + i) * L_ + kc + kg * 4) =
                    make_float4(acc[i][0], acc[i][1], acc[i][2], acc[i][3]);
        }
    }
    __syncthreads();

    // ---- phase 2: softmax per row + write attn weights ----
    {
        const int warp = tid >> 5, lane = tid & 31;
        for (int r = warp; r < QB; r += 8) {
            float* row = scr + r * L_;
            float m = -1e30f;
            for (int k = lane; k < L_; k += 32) m = fmaxf(m, row[k]);
            #pragma unroll
            for (int o = 16; o; o >>= 1) m = fmaxf(m, __shfl_xor_sync(0xffffffffu, m, o));
            float s = 0.f;
            for (int k = lane; k < L_; k += 32) {
                float e = __expf(row[k] - m);
                row[k] = e;
                s += e;
            }
            #pragma unroll
            for (int o = 16; o; o >>= 1) s += __shfl_xor_sync(0xffffffffu, s, o);
            float inv = 1.f / s;
            float* g = attn_out + (((size_t)bb * H_ + hh) * L_ + q0 + r) * L_;
            for (int k = lane; k < L_; k += 32) {
                float w = row[k] * inv;
                row[k] = w;
                g[k] = w;
            }
        }
    }

    // ---- phase 3: ctx = W @ V ----
    {
        const int kslice = tid >> 6;
        const int pos = tid & 63;
        const int qg = pos >> 4;
        const int dg = pos & 15;
        float acc[4][4] = {};

        for (int kc = 0; kc < L_; kc += KC) {
            __syncthreads();
            for (int i4 = tid; i4 < KC * DH_ / 4; i4 += 256)
                ((float4*)kv)[i4] = ((const float4*)(Vh + (size_t)kc * DH_))[i4];
            __syncthreads();

            const int kb = kslice * 64;
            #pragma unroll 4
            for (int kk = 0; kk < 64; kk++) {
                int k = kb + kk;
                float4 v4 = *(const float4*)(kv + k * DH_ + dg * 4);
                #pragma unroll
                for (int i = 0; i < 4; i++) {
                    float w = scr[(qg * 4 + i) * L_ + kc + k];
                    acc[i][0] += w * v4.x;
                    acc[i][1] += w * v4.y;
                    acc[i][2] += w * v4.z;
                    acc[i][3] += w * v4.w;
                }
            }
        }
        __syncthreads();
        #pragma unroll
        for (int i = 0; i < 4; i++)
            #pragma unroll
            for (int j = 0; j < 4; j++)
                kv[kslice * 1024 + (qg * 4 + i) * 64 + dg * 4 + j] = acc[i][j];
        __syncthreads();
        for (int p = tid; p < QB * DH_; p += 256) {
            float v = kv[p] + kv[p + 1024] + kv[p + 2048] + kv[p + 3072];
            int ql = p >> 6, d = p & 63;
            g_ctx[((size_t)bb * L_ + q0 + ql) * D_ + hh * DH_ + d] = v;
        }
    }
}

// ---------------- launch ----------------
extern "C" void kernel_launch(void* const* d_in, const int* in_sizes, int n_in,
                              void* d_out, int out_size)
{
    const float* x  = (const float*)d_in[0];
    const float* Wq = (const float*)d_in[1];
    const float* bq = (const float*)d_in[2];
    const float* Wk = (const float*)d_in[3];
    const float* bk = (const float*)d_in[4];
    const float* Wv = (const float*)d_in[5];
    const float* bv = (const float*)d_in[6];
    const float* Wo = (const float*)d_in[7];
    const float* bo = (const float*)d_in[8];

    float* out  = (float*)d_out;                       // [B, L, D]
    float* attn = out + (size_t)M_ * D_;               // [B, H, L, L]

    cudaFuncSetAttribute(attn_kernel,
                         cudaFuncAttributeMaxDynamicSharedMemorySize, SMEM_BYTES);

    // split inputs to bf16 hi/lo pairs (weights also get swapped copies)
    {
        int n4x = M_ * D_ / 4;
        int n4w = D_ * D_ / 4;
        split_act<<<(n4x + 255) / 256, 256>>>(x, 0, 0, n4x);
        split_w<<<(n4w + 255) / 256, 256>>>(Wq, 0, n4w);
        split_w<<<(n4w + 255) / 256, 256>>>(Wk, 1, n4w);
        split_w<<<(n4w + 255) / 256, 256>>>(Wv, 2, n4w);
        split_w<<<(n4w + 255) / 256, 256>>>(Wo, 3, n4w);
    }

    // QKV projections on tensor cores (WMMA, exact 2-pass)
    dim3 gq(M_ / TM, D_ / TN, 3);
    mma_gemm<<<gq, 256>>>(0, bq, bk, bv, nullptr);

    // attention
    dim3 ga(L_ / QB, H_, B_);
    attn_kernel<<<ga, 256, SMEM_BYTES>>>(attn);

    // split ctx (source resolved in device code — NOT passed from host)
    {
        int n4c = M_ * D_ / 4;
        split_act<<<(n4c + 255) / 256, 256>>>(nullptr, 1, 1, n4c);
    }
    dim3 go(M_ / TM, D_ / TN, 1);
    mma_gemm<<<go, 256>>>(1, bo, bo, bo, out);
}

// round 10
// speedup vs baseline: 1.4770x; 1.0919x over previous
#include <cuda_runtime.h>
#include <cuda_bf16.h>
#include <mma.h>
#include <cstdint>

using namespace nvcuda;

#define B_   2
#define L_   2048
#define D_   1024
#define H_   16
#define DH_  64
#define M_   (B_*L_)          // 4096 rows
#define K2_  2048             // split-K (hi/lo interleaved)
#define SCALE 0.125f          // 1/sqrt(64)

// ---------------- scratch (static device memory; no allocs) ----------------
__device__ float g_q[M_*D_];
__device__ float g_k[M_*D_];
__device__ float g_v[M_*D_];
__device__ float g_ctx[M_*D_];
__device__ __nv_bfloat16 g_xs [M_*K2_];
__device__ __nv_bfloat16 g_cs [M_*K2_];
__device__ __nv_bfloat16 g_wqs[D_*K2_];   // weights, (hi,lo) interleaved
__device__ __nv_bfloat16 g_wks[D_*K2_];
__device__ __nv_bfloat16 g_wvs[D_*K2_];
__device__ __nv_bfloat16 g_wos[D_*K2_];
__device__ __nv_bfloat16 g_wqw[D_*K2_];   // weights, (lo,hi) swapped
__device__ __nv_bfloat16 g_wkw[D_*K2_];
__device__ __nv_bfloat16 g_wvw[D_*K2_];
__device__ __nv_bfloat16 g_wow[D_*K2_];
// attention split operands
__device__ __nv_bfloat16 g_qs [(size_t)B_*H_*L_*128];   // Q*scale (hi,lo)
__device__ __nv_bfloat16 g_qsw[(size_t)B_*H_*L_*128];   // Q*scale (lo,hi)
__device__ __nv_bfloat16 g_ks [(size_t)B_*H_*L_*128];   // K (hi,lo)
__device__ __nv_bfloat16 g_vs [(size_t)B_*H_*DH_*2*L_]; // V^T (hi,lo along key)

// ---------------- hi/lo bf16 pair packing ----------------
__device__ __forceinline__ uint32_t pack_hl(float x) {
    __nv_bfloat16 h = __float2bfloat16(x);
    __nv_bfloat16 l = __float2bfloat16(x - __bfloat162float(h));
    return (uint32_t)__bfloat16_as_ushort(h) |
           ((uint32_t)__bfloat16_as_ushort(l) << 16);
}
__device__ __forceinline__ uint32_t pack_lh(float x) {
    __nv_bfloat16 h = __float2bfloat16(x);
    __nv_bfloat16 l = __float2bfloat16(x - __bfloat162float(h));
    return (uint32_t)__bfloat16_as_ushort(l) |
           ((uint32_t)__bfloat16_as_ushort(h) << 16);
}

// ---------------- split kernels (projection inputs) ----------------
__global__ __launch_bounds__(256)
void split_act(const float* __restrict__ src_param, int src_tag, int dst_tag, int n4)
{
    const float* src = (src_tag == 0) ? src_param : g_ctx;
    __nv_bfloat16* dst = (dst_tag == 0) ? g_xs : g_cs;
    int i = blockIdx.x * 256 + threadIdx.x;
    if (i >= n4) return;
    float4 v = ((const float4*)src)[i];
    uint4 o;
    o.x = pack_hl(v.x); o.y = pack_hl(v.y); o.z = pack_hl(v.z); o.w = pack_hl(v.w);
    ((uint4*)dst)[i] = o;
}

__global__ __launch_bounds__(256)
void split_w(const float* __restrict__ src, int tag, int n4)
{
    __nv_bfloat16* dn = tag == 0 ? g_wqs : tag == 1 ? g_wks : tag == 2 ? g_wvs : g_wos;
    __nv_bfloat16* ds = tag == 0 ? g_wqw : tag == 1 ? g_wkw : tag == 2 ? g_wvw : g_wow;
    int i = blockIdx.x * 256 + threadIdx.x;
    if (i >= n4) return;
    float4 v = ((const float4*)src)[i];
    uint4 on, os;
    on.x = pack_hl(v.x); os.x = pack_lh(v.x);
    on.y = pack_hl(v.y); os.y = pack_lh(v.y);
    on.z = pack_hl(v.z); os.z = pack_lh(v.z);
    on.w = pack_hl(v.w); os.w = pack_lh(v.w);
    ((uint4*)dn)[i] = on;
    ((uint4*)ds)[i] = os;
}

// ---------------- attention operand preparation ----------------
// Q/K split along d: one float4 (4 d's) -> one uint4 (8 bf16)
// n4 MUST cover the FULL [B,H,L,DH] tensors = M_*D_/4 float4 (R9 bug: was M_*DH_/4)
__global__ __launch_bounds__(256)
void qk_split(int n4)
{
    int i = blockIdx.x * 256 + threadIdx.x;
    if (i >= n4) return;
    float4 v = ((const float4*)g_q)[i];
    uint4 on, ow;
    on.x = pack_hl(v.x * SCALE); ow.x = pack_lh(v.x * SCALE);
    on.y = pack_hl(v.y * SCALE); ow.y = pack_lh(v.y * SCALE);
    on.z = pack_hl(v.z * SCALE); ow.z = pack_lh(v.z * SCALE);
    on.w = pack_hl(v.w * SCALE); ow.w = pack_lh(v.w * SCALE);
    ((uint4*)g_qs)[i]  = on;
    ((uint4*)g_qsw)[i] = ow;
    v = ((const float4*)g_k)[i];
    on.x = pack_hl(v.x); on.y = pack_hl(v.y); on.z = pack_hl(v.z); on.w = pack_hl(v.w);
    ((uint4*)g_ks)[i] = on;
}

// V transpose + split along key: g_v [bh][l][d] -> g_vs [bh][d][2l]
__global__ __launch_bounds__(256)
void v_split()
{
    __shared__ float tile[128 * 65];
    const int lb = blockIdx.x;        // 0..15 (128 l's each)
    const int bh = blockIdx.y;        // 0..31
    const int tid = threadIdx.x;
    const float* src = g_v + ((size_t)bh * L_ + lb * 128) * DH_;
    for (int i = 0; i < 8; i++) {
        int u = tid + i * 256;        // 2048 float4
        int r = u >> 4, q = u & 15;
        float4 t = ((const float4*)(src + (size_t)r * DH_))[q];
        tile[r * 65 + q * 4 + 0] = t.x;
        tile[r * 65 + q * 4 + 1] = t.y;
        tile[r * 65 + q * 4 + 2] = t.z;
        tile[r * 65 + q * 4 + 3] = t.w;
    }
    __syncthreads();
    const int d = tid >> 2, part = tid & 3;
    uint32_t* dst = (uint32_t*)g_vs + ((size_t)bh * DH_ + d) * (2 * L_ / 2)
                    + lb * 128 + part * 32;
    #pragma unroll
    for (int j = 0; j < 32; j++) {
        float val = tile[(part * 32 + j) * 65 + d];
        dst[j] = pack_hl(val);
    }
}

// ---------------- WMMA GEMM (projections) ----------------
#define TM 128
#define TN 128
#define BK 32
#define NCH (K2_ / BK)        // 64
#define AS 40
#define STG 20

__global__ __launch_bounds__(256)
void mma_gemm(int which,
              const float* __restrict__ bi0, const float* __restrict__ bi1,
              const float* __restrict__ bi2, float* __restrict__ out_dst)
{
    __shared__ __align__(16) __nv_bfloat16 sA[TM][AS];
    __shared__ __align__(16) __nv_bfloat16 sB[TN][AS];
    __shared__ __align__(16) float stage[8][16 * STG];

    const int mat = blockIdx.z;
    const __nv_bfloat16* A = (which == 0) ? g_xs : g_cs;
    const __nv_bfloat16* Bn =
        (which == 1) ? g_wos : (mat == 0 ? g_wqs : (mat == 1 ? g_wks : g_wvs));
    const __nv_bfloat16* Bw =
        (which == 1) ? g_wow : (mat == 0 ? g_wqw : (mat == 1 ? g_wkw : g_wvw));
    const float* bias = (mat == 0) ? bi0 : (mat == 1 ? bi1 : bi2);
    float* dsel = (mat == 0) ? g_q : (mat == 1 ? g_k : g_v);

    const int row0 = blockIdx.x * TM;
    const int col0 = blockIdx.y * TN;
    const int tid  = threadIdx.x;
    const int wid  = tid >> 5, lane = tid & 31;
    const int wr   = wid >> 2;
    const int wc   = wid & 3;

    wmma::fragment<wmma::accumulator, 16, 16, 16, float> acc[4][2];
    #pragma unroll
    for (int i = 0; i < 4; i++)
        #pragma unroll
        for (int j = 0; j < 2; j++)
            wmma::fill_fragment(acc[i][j], 0.0f);

    const int r0c = tid >> 2,          q0c = tid & 3;
    const int r1c = (tid + 256) >> 2,  q1c = (tid + 256) & 3;

    for (int pass = 0; pass < 2; pass++) {
        const __nv_bfloat16* Bp = pass ? Bw : Bn;
        for (int ch = 0; ch < NCH; ch++) {
            const int k0g = ch * BK;
            __syncthreads();
            *(uint4*)&sA[r0c][q0c * 8] =
                *(const uint4*)(A  + (size_t)(row0 + r0c) * K2_ + k0g + q0c * 8);
            *(uint4*)&sA[r1c][q1c * 8] =
                *(const uint4*)(A  + (size_t)(row0 + r1c) * K2_ + k0g + q1c * 8);
            *(uint4*)&sB[r0c][q0c * 8] =
                *(const uint4*)(Bp + (size_t)(col0 + r0c) * K2_ + k0g + q0c * 8);
            *(uint4*)&sB[r1c][q1c * 8] =
                *(const uint4*)(Bp + (size_t)(col0 + r1c) * K2_ + k0g + q1c * 8);
            __syncthreads();

            #pragma unroll
            for (int kk = 0; kk < 2; kk++) {
                const int k0 = kk * 16;
                wmma::fragment<wmma::matrix_a, 16, 16, 16, __nv_bfloat16,
                               wmma::row_major> af[4];
                #pragma unroll
                for (int i = 0; i < 4; i++)
                    wmma::load_matrix_sync(af[i], &sA[wr * 64 + i * 16][k0], AS);
                wmma::fragment<wmma::matrix_b, 16, 16, 16, __nv_bfloat16,
                               wmma::col_major> bf[2];
                #pragma unroll
                for (int j = 0; j < 2; j++)
                    wmma::load_matrix_sync(bf[j], &sB[wc * 32 + j * 16][k0], AS);
                #pragma unroll
                for (int i = 0; i < 4; i++)
                    #pragma unroll
                    for (int j = 0; j < 2; j++)
                        wmma::mma_sync(acc[i][j], af[i], bf[j], acc[i][j]);
            }
        }
    }

    __syncthreads();
    #pragma unroll
    for (int i = 0; i < 4; i++) {
        #pragma unroll
        for (int j = 0; j < 2; j++) {
            wmma::store_matrix_sync(&stage[wid][0], acc[i][j], STG,
                                    wmma::mem_row_major);
            __syncwarp();
            #pragma unroll
            for (int e = 0; e < 8; e++) {
                int idx = lane * 8 + e;
                int rr = idx >> 4, cc = idx & 15;
                int m = row0 + wr * 64 + i * 16 + rr;
                int n = col0 + wc * 32 + j * 16 + cc;
                float v = stage[wid][rr * STG + cc] + bias[n];
                if (which == 1) {
                    out_dst[(size_t)m * D_ + n] = v;
                } else {
                    int l = m & (L_ - 1), bb = m >> 11;
                    int h = n >> 6, d = n & 63;
                    dsel[(((size_t)bb * H_ + h) * L_ + l) * DH_ + d] = v;
                }
            }
            __syncwarp();
        }
    }
}

// ---------------- WMMA attention ----------------
// grid (L/16, H, B), 256 threads (8 warps). Exact 2-pass split everywhere.
#define QB2  16
#define LD_S 2064             // scr row stride (fp32)
#define LD_K 136              // bf16 ldm for K chunk / Q tiles
#define LD_V 264              // bf16 ldm for Vt chunk / W tiles
#define OFF_B    (QB2*LD_S*4)            // 132096
#define OFF_AN   (OFF_B + 34816)         // 166912
#define OFF_AW   (OFF_AN + 8448)         // 175360
#define OFF_RED  (OFF_AN + 16896)        // 183808
#define SM2_BYTES (OFF_RED + 8192)       // 192000

__global__ __launch_bounds__(256)
void attn_wmma(float* __restrict__ attn_out)
{
    extern __shared__ char smraw[];
    float* scr = (float*)smraw;                          // [16][LD_S]
    __nv_bfloat16* bB  = (__nv_bfloat16*)(smraw + OFF_B);
    __nv_bfloat16* bAn = (__nv_bfloat16*)(smraw + OFF_AN);
    __nv_bfloat16* bAw = (__nv_bfloat16*)(smraw + OFF_AW);
    float* red = (float*)(smraw + OFF_RED);

    const int q0 = blockIdx.x * QB2;
    const int hh = blockIdx.y, bb = blockIdx.z;
    const int tid = threadIdx.x, wid = tid >> 5, lane = tid & 31;
    const int bh = bb * H_ + hh;

    const __nv_bfloat16* Qn = g_qs  + ((size_t)bh * L_ + q0) * 128;
    const __nv_bfloat16* Qw = g_qsw + ((size_t)bh * L_ + q0) * 128;
    const __nv_bfloat16* Kh = g_ks  + (size_t)bh * L_ * 128;
    const __nv_bfloat16* Vt = g_vs  + (size_t)bh * DH_ * (2 * L_);

    // load Q tiles (16 x 128 bf16 each) into bAn/bAw, ldm LD_K
    for (int u = tid; u < 512; u += 256) {
        int half = u >> 8;
        int v = u & 255;
        int r = v >> 4, q = v & 15;
        uint4 src = ((const uint4*)((half ? Qw : Qn) + r * 128))[q];
        __nv_bfloat16* dst = half ? bAw : bAn;
        *(uint4*)(dst + r * LD_K + q * 8) = src;
    }

    // ---- phase 1: scores ----
    {
        wmma::fragment<wmma::accumulator, 16, 16, 16, float> sacc;
        for (int kc = 0; kc < L_; kc += 128) {
            __syncthreads();
            #pragma unroll
            for (int i = 0; i < 8; i++) {
                int u = tid + i * 256;           // 2048 uint4
                int r = u >> 4, q = u & 15;
                *(uint4*)(bB + r * LD_K + q * 8) =
                    ((const uint4*)(Kh + (size_t)(kc + r) * 128))[q];
            }
            __syncthreads();
            wmma::fill_fragment(sacc, 0.0f);
            #pragma unroll
            for (int kt = 0; kt < 8; kt++) {
                wmma::fragment<wmma::matrix_a, 16, 16, 16, __nv_bfloat16,
                               wmma::row_major> a;
                wmma::fragment<wmma::matrix_b, 16, 16, 16, __nv_bfloat16,
                               wmma::col_major> b;
                wmma::load_matrix_sync(b, bB + (size_t)wid * 16 * LD_K + kt * 16, LD_K);
                wmma::load_matrix_sync(a, bAn + kt * 16, LD_K);
                wmma::mma_sync(sacc, a, b, sacc);
                wmma::load_matrix_sync(a, bAw + kt * 16, LD_K);
                wmma::mma_sync(sacc, a, b, sacc);
            }
            wmma::store_matrix_sync(scr + kc + wid * 16, sacc, LD_S,
                                    wmma::mem_row_major);
        }
    }
    __syncthreads();

    // ---- phase 2: softmax + write attention weights ----
    for (int r = wid; r < QB2; r += 8) {
        float* row = scr + (size_t)r * LD_S;
        float m = -1e30f;
        for (int k = lane; k < L_; k += 32) m = fmaxf(m, row[k]);
        #pragma unroll
        for (int o = 16; o; o >>= 1) m = fmaxf(m, __shfl_xor_sync(0xffffffffu, m, o));
        float s = 0.f;
        for (int k = lane; k < L_; k += 32) {
            float e = __expf(row[k] - m);
            row[k] = e;
            s += e;
        }
        #pragma unroll
        for (int o = 16; o; o >>= 1) s += __shfl_xor_sync(0xffffffffu, s, o);
        float inv = 1.f / s;
        float* g = attn_out + ((size_t)bh * L_ + q0 + r) * L_;
        for (int k = lane; k < L_; k += 32) {
            float w = row[k] * inv;
            row[k] = w;
            g[k] = w;
        }
    }

    // ---- phase 3: ctx = W @ V ----
    {
        wmma::fragment<wmma::accumulator, 16, 16, 16, float> cacc;
        wmma::fill_fragment(cacc, 0.0f);
        const int nt = wid >> 1, kh = wid & 1;
        const int wr2 = tid >> 4, wks = (tid & 15) * 8;
        for (int c = 0; c < 16; c++) {               // 16 chunks x 128 keys
            __syncthreads();
            // Vt chunk [64][256 bf16] -> bB, ldm LD_V
            #pragma unroll
            for (int i = 0; i < 8; i++) {
                int u = tid + i * 256;               // 2048 uint4
                int r = u >> 5, q = u & 31;
                *(uint4*)(bB + r * LD_V + q * 8) =
                    ((const uint4*)(Vt + (size_t)r * (2 * L_) + c * 256))[q];
            }
            // W chunk -> bAn (hi,lo), bAw (lo,hi): 16 rows x 128 keys
            {
                const float* srow = scr + (size_t)wr2 * LD_S + c * 128 + wks;
                uint32_t* wn = (uint32_t*)bAn + wr2 * (LD_V / 2) + wks;
                uint32_t* ww = (uint32_t*)bAw + wr2 * (LD_V / 2) + wks;
                #pragma unroll
                for (int j = 0; j < 8; j++) {
                    float w = srow[j];
                    wn[j] = pack_hl(w);
                    ww[j] = pack_lh(w);
                }
            }
            __syncthreads();
            #pragma unroll
            for (int kt = 0; kt < 8; kt++) {
                int k0 = kh * 128 + kt * 16;
                wmma::fragment<wmma::matrix_a, 16, 16, 16, __nv_bfloat16,
                               wmma::row_major> a;
                wmma::fragment<wmma::matrix_b, 16, 16, 16, __nv_bfloat16,
                               wmma::col_major> b;
                wmma::load_matrix_sync(b, bB + (size_t)nt * 16 * LD_V + k0, LD_V);
                wmma::load_matrix_sync(a, bAn + k0, LD_V);
                wmma::mma_sync(cacc, a, b, cacc);
                wmma::load_matrix_sync(a, bAw + k0, LD_V);
                wmma::mma_sync(cacc, a, b, cacc);
            }
        }
        __syncthreads();
        wmma::store_matrix_sync(red + wid * 256, cacc, 16, wmma::mem_row_major);
        __syncthreads();
        for (int e = tid; e < 1024; e += 256) {
            int m = e >> 6, col = e & 63;
            int w0 = (col >> 4) << 1;
            float v = red[w0 * 256 + m * 16 + (col & 15)]
                    + red[(w0 + 1) * 256 + m * 16 + (col & 15)];
            g_ctx[((size_t)bb * L_ + q0 + m) * D_ + hh * 64 + col] = v;
        }
    }
}

// ---------------- launch ----------------
extern "C" void kernel_launch(void* const* d_in, const int* in_sizes, int n_in,
                              void* d_out, int out_size)
{
    const float* x  = (const float*)d_in[0];
    const float* Wq = (const float*)d_in[1];
    const float* bq = (const float*)d_in[2];
    const float* Wk = (const float*)d_in[3];
    const float* bk = (const float*)d_in[4];
    const float* Wv = (const float*)d_in[5];
    const float* bv = (const float*)d_in[6];
    const float* Wo = (const float*)d_in[7];
    const float* bo = (const float*)d_in[8];

    float* out  = (float*)d_out;                       // [B, L, D]
    float* attn = out + (size_t)M_ * D_;               // [B, H, L, L]

    cudaFuncSetAttribute(attn_wmma,
                         cudaFuncAttributeMaxDynamicSharedMemorySize, SM2_BYTES);

    // split projection inputs
    {
        int n4x = M_ * D_ / 4;
        int n4w = D_ * D_ / 4;
        split_act<<<(n4x + 255) / 256, 256>>>(x, 0, 0, n4x);
        split_w<<<(n4w + 255) / 256, 256>>>(Wq, 0, n4w);
        split_w<<<(n4w + 255) / 256, 256>>>(Wk, 1, n4w);
        split_w<<<(n4w + 255) / 256, 256>>>(Wv, 2, n4w);
        split_w<<<(n4w + 255) / 256, 256>>>(Wo, 3, n4w);
    }

    // QKV projections
    dim3 gq(M_ / TM, D_ / TN, 3);
    mma_gemm<<<gq, 256>>>(0, bq, bk, bv, nullptr);

    // prepare attention operands (split Q/K, transpose+split V)
    {
        int n4 = M_ * D_ / 4;    // FULL [B,H,L,DH] element count / 4 (R9 fix)
        qk_split<<<(n4 + 255) / 256, 256>>>(n4);
        dim3 gv(L_ / 128, B_ * H_);
        v_split<<<gv, 256>>>();
    }

    // attention (wmma, exact split)
    dim3 ga(L_ / QB2, H_, B_);
    attn_wmma<<<ga, 256, SM2_BYTES>>>(attn);

    // split ctx (device-resolved source), output projection
    {
        int n4c = M_ * D_ / 4;
        split_act<<<(n4c + 255) / 256, 256>>>(nullptr, 1, 1, n4c);
    }
    dim3 go(M_ / TM, D_ / TN, 1);
    mma_gemm<<<go, 256>>>(1, bo, bo, bo, out);
}